// round 7
// baseline (speedup 1.0000x reference)
#include <cuda_runtime.h>
#include <math.h>

// Problem constants (fixed by the reference setup)
constexpr int NN   = 512;
constexpr int JJ   = 20000;
constexpr int DIMM = JJ - 1;    // 19999 softmax logit columns (pivot dropped)
constexpr int PP   = 8;
constexpr int JT   = 256;                         // threads per block (j dimension)
constexpr int JB   = (JJ + JT - 1) / JT;          // 79 j-blocks
constexpr int RB   = 16;                          // row chunks
constexpr int ROWS_PER = NN / RB;                 // 32 rows per block
constexpr int LFMAX = 2048;                       // log-factorial table size

// Scratch (device globals: no allocations allowed)
__device__ float  g_r[JJ];          // 1 / softplus(phi)
__device__ float  g_logr[JJ];       // log(r)
__device__ float  g_lgr[JJ];        // lgamma(r)
__device__ float  g_lf[LFMAX];      // lgamma(i + 1) = log(i!)
__device__ float  g_pexp[JB * NN];  // partial sum of exp(logits) per (jblock, row)
__device__ float  g_ps[JB * NN];    // partial sum of Y per (jblock, row)
__device__ float  g_lse[NN];        // logsumexp per row
__device__ float  g_logs[NN];       // log(sum Y) per row
__device__ float  g_s[NN];          // sum Y per row
__device__ double g_part[JB * RB];  // per-block loglik partials

// ---------------------------------------------------------------------------
// Kernel 1: per-gene precompute + log-factorial table
// ---------------------------------------------------------------------------
__global__ void k_prep(const float* __restrict__ phi) {
    int i = blockIdx.x * blockDim.x + threadIdx.x;
    if (i < JJ) {
        float ph = phi[i];
        // softplus(x) = max(x,0) + log1p(exp(-|x|))
        float sp = fmaxf(ph, 0.0f) + log1pf(expf(-fabsf(ph)));
        float r  = 1.0f / sp;
        g_r[i]    = r;
        g_logr[i] = -logf(sp);      // log(1/sp)
        g_lgr[i]  = lgammaf(r);
    }
    if (i < LFMAX) {
        g_lf[i] = lgammaf((float)i + 1.0f);
    }
}

// ---------------------------------------------------------------------------
// Kernel 2: j-major row statistics: partial sum(exp(logit)) and sum(Y) per row
// Each thread owns ONE j column (mu + 8 betas hoisted into registers) and
// loops over 32 rows; 2-stage deterministic reduction via g_pexp/g_ps.
// ---------------------------------------------------------------------------
__global__ void k_rowpart(const float* __restrict__ mu,
                          const float* __restrict__ beta,
                          const float* __restrict__ X,
                          const float* __restrict__ Y) {
    const int tid  = threadIdx.x;
    const int j    = blockIdx.x * JT + tid;
    const bool valid = (j < JJ);
    const bool hasb  = (j < DIMM);

    float mu_j = 0.0f;
    float b[PP];
#pragma unroll
    for (int p = 0; p < PP; p++) b[p] = 0.0f;
    if (hasb) {
        mu_j = mu[j];
#pragma unroll
        for (int p = 0; p < PP; p++) b[p] = beta[(size_t)p * DIMM + j];
    }

    const int n0 = blockIdx.y * ROWS_PER;
    __shared__ float sx[ROWS_PER * PP];   // X rows for this chunk (256 floats)
    if (tid < ROWS_PER * PP) sx[tid] = X[(size_t)n0 * PP + tid];
    __shared__ float s_e[8], s_y[8];
    __syncthreads();

    const int lane = tid & 31, wid = tid >> 5;

    for (int ni = 0; ni < ROWS_PER; ni++) {
        const int n = n0 + ni;
        float xb = mu_j;
#pragma unroll
        for (int p = 0; p < PP; p++) xb = fmaf(sx[ni * PP + p], b[p], xb);
        // pivot column (j == DIMM): mu_j = b = 0 -> xb = 0 -> exp = 1 (correct)
        float e = valid ? expf(xb) : 0.0f;
        float y = valid ? Y[(size_t)n * JJ + j] : 0.0f;
#pragma unroll
        for (int off = 16; off > 0; off >>= 1) {
            e += __shfl_down_sync(0xffffffffu, e, off);
            y += __shfl_down_sync(0xffffffffu, y, off);
        }
        if (lane == 0) { s_e[wid] = e; s_y[wid] = y; }
        __syncthreads();
        if (wid == 0) {
            float ee = (lane < 8) ? s_e[lane] : 0.0f;
            float yy = (lane < 8) ? s_y[lane] : 0.0f;
#pragma unroll
            for (int off = 4; off > 0; off >>= 1) {
                ee += __shfl_down_sync(0xffffffffu, ee, off);
                yy += __shfl_down_sync(0xffffffffu, yy, off);
            }
            if (lane == 0) {
                g_pexp[blockIdx.x * NN + n] = ee;
                g_ps[blockIdx.x * NN + n]   = yy;
            }
        }
        __syncthreads();
    }
}

// ---------------------------------------------------------------------------
// Kernel 3: finalize row stats (deterministic serial reduce over 79 partials)
// ---------------------------------------------------------------------------
__global__ void k_rowfinal() {
    int n = blockIdx.x * blockDim.x + threadIdx.x;
    if (n >= NN) return;
    double se = 0.0;
    float  ss = 0.0f;
    for (int i = 0; i < JB; i++) {
        se += (double)g_pexp[i * NN + n];   // coalesced across n
        ss += g_ps[i * NN + n];             // exact: integer partial sums < 2^24
    }
    g_lse[n]  = (float)log(se);
    g_s[n]    = ss;
    g_logs[n] = logf(ss);
}

// ---------------------------------------------------------------------------
// Kernel 4: main NB log-likelihood accumulation (j-major, double accumulate)
// ---------------------------------------------------------------------------
__global__ void k_main(const float* __restrict__ mu,
                       const float* __restrict__ beta,
                       const float* __restrict__ X,
                       const float* __restrict__ Y) {
    const int tid  = threadIdx.x;
    const int j    = blockIdx.x * JT + tid;
    const bool valid = (j < JJ);
    const bool hasb  = (j < DIMM);

    float r = 1.0f, logr = 0.0f, lgr = 0.0f;
    if (valid) { r = g_r[j]; logr = g_logr[j]; lgr = g_lgr[j]; }
    float mu_j = 0.0f;
    float b[PP];
#pragma unroll
    for (int p = 0; p < PP; p++) b[p] = 0.0f;
    if (hasb) {
        mu_j = mu[j];
#pragma unroll
        for (int p = 0; p < PP; p++) b[p] = beta[(size_t)p * DIMM + j];
    }

    const int n0 = blockIdx.y * ROWS_PER;
    __shared__ float sx[ROWS_PER * PP];
    if (tid < ROWS_PER * PP) sx[tid] = X[(size_t)n0 * PP + tid];
    __syncthreads();

    double acc = 0.0;
    for (int ni = 0; ni < ROWS_PER; ni++) {
        const int n = n0 + ni;
        const float lse  = g_lse[n];
        const float logs = g_logs[n];
        const float s    = g_s[n];
        float xb = mu_j;
#pragma unroll
        for (int p = 0; p < PP; p++) xb = fmaf(sx[ni * PP + p], b[p], xb);
        const float t   = xb - lse;            // log(pi)
        const float m   = s * expf(t);         // mean
        const float lrm = logf(r + m);         // log(r + mean)
        float y = valid ? Y[(size_t)n * JJ + j] : 0.0f;
        float term = 0.0f;
        if (valid) {
            int yi = (int)(y + 0.5f);          // Y is integer-valued
            float lgy1 = (yi >= 0 && yi < LFMAX) ? g_lf[yi] : lgammaf(y + 1.0f);
            term = lgammaf(y + r) - lgr - lgy1
                 + r * (logr - lrm)
                 + y * (logs + t - lrm);       // log(mean) = log s + t
        }
        acc += (double)term;
    }

    // block reduction of double acc
    const int lane = tid & 31, wid = tid >> 5;
    __shared__ double sd[8];
#pragma unroll
    for (int off = 16; off > 0; off >>= 1)
        acc += __shfl_down_sync(0xffffffffu, acc, off);
    if (lane == 0) sd[wid] = acc;
    __syncthreads();
    if (wid == 0) {
        double v = (lane < 8) ? sd[lane] : 0.0;
#pragma unroll
        for (int off = 4; off > 0; off >>= 1)
            v += __shfl_down_sync(0xffffffffu, v, off);
        if (lane == 0) g_part[blockIdx.y * JB + blockIdx.x] = v;
    }
}

// ---------------------------------------------------------------------------
// Kernel 5: deterministic final reduction -> float scalar
// ---------------------------------------------------------------------------
__global__ void k_finish(float* __restrict__ out) {
    const int tid = threadIdx.x;
    double a = 0.0;
    for (int i = tid; i < JB * RB; i += blockDim.x) a += g_part[i];
    const int lane = tid & 31, wid = tid >> 5;
    __shared__ double sd[8];
#pragma unroll
    for (int off = 16; off > 0; off >>= 1)
        a += __shfl_down_sync(0xffffffffu, a, off);
    if (lane == 0) sd[wid] = a;
    __syncthreads();
    if (wid == 0) {
        double v = (lane < 8) ? sd[lane] : 0.0;
#pragma unroll
        for (int off = 4; off > 0; off >>= 1)
            v += __shfl_down_sync(0xffffffffu, v, off);
        if (lane == 0) out[0] = (float)v;
    }
}

// ---------------------------------------------------------------------------
extern "C" void kernel_launch(void* const* d_in, const int* in_sizes, int n_in,
                              void* d_out, int out_size) {
    const float* mu   = (const float*)d_in[0];   // [DIMM]
    const float* beta = (const float*)d_in[1];   // [PP * DIMM]
    const float* phi  = (const float*)d_in[2];   // [JJ]
    const float* X    = (const float*)d_in[3];   // [NN, PP]
    const float* Y    = (const float*)d_in[4];   // [NN, JJ]
    float* out = (float*)d_out;

    k_prep<<<JB, JT>>>(phi);
    k_rowpart<<<dim3(JB, RB), JT>>>(mu, beta, X, Y);
    k_rowfinal<<<(NN + 255) / 256, 256>>>();
    k_main<<<dim3(JB, RB), JT>>>(mu, beta, X, Y);
    k_finish<<<1, 256>>>(out);
}

// round 8
// speedup vs baseline: 1.0014x; 1.0014x over previous
#include <cuda_runtime.h>
#include <math.h>

// Problem constants (fixed by the reference setup)
constexpr int NN   = 512;
constexpr int JJ   = 20000;
constexpr int DIMM = JJ - 1;    // 19999 softmax logit columns (pivot dropped)
constexpr int PP   = 8;
constexpr int JT   = 256;                         // threads per block (j dimension)
constexpr int JB   = (JJ + JT - 1) / JT;          // 79 j-blocks
constexpr int RB   = 16;                          // row chunks
constexpr int ROWS_PER = NN / RB;                 // 32 rows per block
constexpr int LFMAX = 2048;                       // log-factorial table size

// Scratch (device globals: no allocations allowed)
__device__ float  g_r[JJ];          // 1 / softplus(phi)
__device__ float  g_logr[JJ];       // log(r)
__device__ float  g_lgr[JJ];        // lgamma(r)
__device__ float  g_lf[LFMAX];      // lgamma(i + 1) = log(i!)
__device__ float  g_pexp[JB * NN];  // partial sum of exp(logits) per (jblock, row)
__device__ float  g_ps[JB * NN];    // partial sum of Y per (jblock, row)
__device__ float  g_lse[NN];        // logsumexp per row
__device__ float  g_logs[NN];       // log(sum Y) per row
__device__ float  g_s[NN];          // sum Y per row
__device__ double g_part[JB * RB];  // per-block loglik partials

// ---------------------------------------------------------------------------
// Kernel 1: per-gene precompute + log-factorial table
// ---------------------------------------------------------------------------
__global__ void k_prep(const float* __restrict__ phi) {
    int i = blockIdx.x * blockDim.x + threadIdx.x;
    if (i < JJ) {
        float ph = phi[i];
        // softplus(x) = max(x,0) + log1p(exp(-|x|))
        float sp = fmaxf(ph, 0.0f) + log1pf(expf(-fabsf(ph)));
        float r  = 1.0f / sp;
        g_r[i]    = r;
        g_logr[i] = -logf(sp);      // log(1/sp)
        g_lgr[i]  = lgammaf(r);
    }
    if (i < LFMAX) {
        g_lf[i] = lgammaf((float)i + 1.0f);
    }
}

// ---------------------------------------------------------------------------
// Kernel 2: j-major row statistics: partial sum(exp(logit)) and sum(Y) per row
// Each thread owns ONE j column (mu + 8 betas hoisted into registers) and
// loops over 32 rows; 2-stage deterministic reduction via g_pexp/g_ps.
// ---------------------------------------------------------------------------
__global__ void k_rowpart(const float* __restrict__ mu,
                          const float* __restrict__ beta,
                          const float* __restrict__ X,
                          const float* __restrict__ Y) {
    const int tid  = threadIdx.x;
    const int j    = blockIdx.x * JT + tid;
    const bool valid = (j < JJ);
    const bool hasb  = (j < DIMM);

    float mu_j = 0.0f;
    float b[PP];
#pragma unroll
    for (int p = 0; p < PP; p++) b[p] = 0.0f;
    if (hasb) {
        mu_j = mu[j];
#pragma unroll
        for (int p = 0; p < PP; p++) b[p] = beta[(size_t)p * DIMM + j];
    }

    const int n0 = blockIdx.y * ROWS_PER;
    __shared__ float sx[ROWS_PER * PP];   // X rows for this chunk (256 floats)
    if (tid < ROWS_PER * PP) sx[tid] = X[(size_t)n0 * PP + tid];
    __shared__ float s_e[8], s_y[8];
    __syncthreads();

    const int lane = tid & 31, wid = tid >> 5;

    for (int ni = 0; ni < ROWS_PER; ni++) {
        const int n = n0 + ni;
        float xb = mu_j;
#pragma unroll
        for (int p = 0; p < PP; p++) xb = fmaf(sx[ni * PP + p], b[p], xb);
        // pivot column (j == DIMM): mu_j = b = 0 -> xb = 0 -> exp = 1 (correct)
        float e = valid ? expf(xb) : 0.0f;
        float y = valid ? Y[(size_t)n * JJ + j] : 0.0f;
#pragma unroll
        for (int off = 16; off > 0; off >>= 1) {
            e += __shfl_down_sync(0xffffffffu, e, off);
            y += __shfl_down_sync(0xffffffffu, y, off);
        }
        if (lane == 0) { s_e[wid] = e; s_y[wid] = y; }
        __syncthreads();
        if (wid == 0) {
            float ee = (lane < 8) ? s_e[lane] : 0.0f;
            float yy = (lane < 8) ? s_y[lane] : 0.0f;
#pragma unroll
            for (int off = 4; off > 0; off >>= 1) {
                ee += __shfl_down_sync(0xffffffffu, ee, off);
                yy += __shfl_down_sync(0xffffffffu, yy, off);
            }
            if (lane == 0) {
                g_pexp[blockIdx.x * NN + n] = ee;
                g_ps[blockIdx.x * NN + n]   = yy;
            }
        }
        __syncthreads();
    }
}

// ---------------------------------------------------------------------------
// Kernel 3: finalize row stats (deterministic serial reduce over 79 partials)
// ---------------------------------------------------------------------------
__global__ void k_rowfinal() {
    int n = blockIdx.x * blockDim.x + threadIdx.x;
    if (n >= NN) return;
    double se = 0.0;
    float  ss = 0.0f;
    for (int i = 0; i < JB; i++) {
        se += (double)g_pexp[i * NN + n];   // coalesced across n
        ss += g_ps[i * NN + n];             // exact: integer partial sums < 2^24
    }
    g_lse[n]  = (float)log(se);
    g_s[n]    = ss;
    g_logs[n] = logf(ss);
}

// ---------------------------------------------------------------------------
// Kernel 4: main NB log-likelihood accumulation (j-major, double accumulate)
// ---------------------------------------------------------------------------
__global__ void k_main(const float* __restrict__ mu,
                       const float* __restrict__ beta,
                       const float* __restrict__ X,
                       const float* __restrict__ Y) {
    const int tid  = threadIdx.x;
    const int j    = blockIdx.x * JT + tid;
    const bool valid = (j < JJ);
    const bool hasb  = (j < DIMM);

    float r = 1.0f, logr = 0.0f, lgr = 0.0f;
    if (valid) { r = g_r[j]; logr = g_logr[j]; lgr = g_lgr[j]; }
    float mu_j = 0.0f;
    float b[PP];
#pragma unroll
    for (int p = 0; p < PP; p++) b[p] = 0.0f;
    if (hasb) {
        mu_j = mu[j];
#pragma unroll
        for (int p = 0; p < PP; p++) b[p] = beta[(size_t)p * DIMM + j];
    }

    const int n0 = blockIdx.y * ROWS_PER;
    __shared__ float sx[ROWS_PER * PP];
    if (tid < ROWS_PER * PP) sx[tid] = X[(size_t)n0 * PP + tid];
    __syncthreads();

    double acc = 0.0;
    for (int ni = 0; ni < ROWS_PER; ni++) {
        const int n = n0 + ni;
        const float lse  = g_lse[n];
        const float logs = g_logs[n];
        const float s    = g_s[n];
        float xb = mu_j;
#pragma unroll
        for (int p = 0; p < PP; p++) xb = fmaf(sx[ni * PP + p], b[p], xb);
        const float t   = xb - lse;            // log(pi)
        const float m   = s * expf(t);         // mean
        const float lrm = logf(r + m);         // log(r + mean)
        float y = valid ? Y[(size_t)n * JJ + j] : 0.0f;
        float term = 0.0f;
        if (valid) {
            int yi = (int)(y + 0.5f);          // Y is integer-valued
            float lgy1 = (yi >= 0 && yi < LFMAX) ? g_lf[yi] : lgammaf(y + 1.0f);
            term = lgammaf(y + r) - lgr - lgy1
                 + r * (logr - lrm)
                 + y * (logs + t - lrm);       // log(mean) = log s + t
        }
        acc += (double)term;
    }

    // block reduction of double acc
    const int lane = tid & 31, wid = tid >> 5;
    __shared__ double sd[8];
#pragma unroll
    for (int off = 16; off > 0; off >>= 1)
        acc += __shfl_down_sync(0xffffffffu, acc, off);
    if (lane == 0) sd[wid] = acc;
    __syncthreads();
    if (wid == 0) {
        double v = (lane < 8) ? sd[lane] : 0.0;
#pragma unroll
        for (int off = 4; off > 0; off >>= 1)
            v += __shfl_down_sync(0xffffffffu, v, off);
        if (lane == 0) g_part[blockIdx.y * JB + blockIdx.x] = v;
    }
}

// ---------------------------------------------------------------------------
// Kernel 5: deterministic final reduction -> float scalar
// ---------------------------------------------------------------------------
__global__ void k_finish(float* __restrict__ out) {
    const int tid = threadIdx.x;
    double a = 0.0;
    for (int i = tid; i < JB * RB; i += blockDim.x) a += g_part[i];
    const int lane = tid & 31, wid = tid >> 5;
    __shared__ double sd[8];
#pragma unroll
    for (int off = 16; off > 0; off >>= 1)
        a += __shfl_down_sync(0xffffffffu, a, off);
    if (lane == 0) sd[wid] = a;
    __syncthreads();
    if (wid == 0) {
        double v = (lane < 8) ? sd[lane] : 0.0;
#pragma unroll
        for (int off = 4; off > 0; off >>= 1)
            v += __shfl_down_sync(0xffffffffu, v, off);
        if (lane == 0) out[0] = (float)v;
    }
}

// ---------------------------------------------------------------------------
extern "C" void kernel_launch(void* const* d_in, const int* in_sizes, int n_in,
                              void* d_out, int out_size) {
    const float* mu   = (const float*)d_in[0];   // [DIMM]
    const float* beta = (const float*)d_in[1];   // [PP * DIMM]
    const float* phi  = (const float*)d_in[2];   // [JJ]
    const float* X    = (const float*)d_in[3];   // [NN, PP]
    const float* Y    = (const float*)d_in[4];   // [NN, JJ]
    float* out = (float*)d_out;

    k_prep<<<JB, JT>>>(phi);
    k_rowpart<<<dim3(JB, RB), JT>>>(mu, beta, X, Y);
    k_rowfinal<<<(NN + 255) / 256, 256>>>();
    k_main<<<dim3(JB, RB), JT>>>(mu, beta, X, Y);
    k_finish<<<1, 256>>>(out);
}